// round 7
// baseline (speedup 1.0000x reference)
#include <cuda_runtime.h>

#define NN 100000
#define L1_BLOCKS 592   // 4 CTAs/SM on 148 SMs

// ---- scratch (static __device__ globals; no allocation) ----
__device__ int    g_deg[NN];             // zero at load; node_prep resets each run
__device__ float4 g_S[NN];               // {S.xyz accum, w=dinv[v] (preserved)}
__device__ float4 g_Q[NN];               // {sx.xyz, w-accum (init dinv = self-loop)}
__device__ float  g_part[L1_BLOCKS][16]; // per-block layer-2 partials

// ---------------------------------------------------------------------------
// degree histogram over dst (self-loop added in node_prep)
__global__ void k_hist(const int* __restrict__ dst, int E) {
    int i      = blockIdx.x * blockDim.x + threadIdx.x;
    int stride = gridDim.x * blockDim.x;
    for (int e = i; e < E; e += stride) {
        atomicAdd(&g_deg[dst[e]], 1);
    }
}

// per-node: dinv = rsqrt(deg+1); S = {0,0,0,dinv}; Q = {dinv*x, dinv}; reset deg
__global__ void k_node_prep(const float* __restrict__ x) {
    int v = blockIdx.x * blockDim.x + threadIdx.x;
    if (v >= NN) return;
    float d = rsqrtf((float)(g_deg[v] + 1));
    g_deg[v] = 0;                        // deterministic across graph replays
    g_S[v] = make_float4(0.f, 0.f, 0.f, d);
    g_Q[v] = make_float4(d * x[3 * v + 0], d * x[3 * v + 1], d * x[3 * v + 2], d);
}

// fused edge pass, 4 divergent lanes per edge:
//   gather Q[s] (16B), load S[d].w = dinv[d] (4B, stable word),
//   red.v4 S[d] += {sx, 0}  (w lane preserved),
//   red Q[s].w += dinv[d]   (layer-2 source weight)
__global__ void k_scatter(const int* __restrict__ src,
                          const int* __restrict__ dst, int E) {
    int i      = blockIdx.x * blockDim.x + threadIdx.x;
    int stride = gridDim.x * blockDim.x;
    for (int e = i; e < E; e += stride) {
        int s = src[e];
        int d = dst[e];
        float4 q  = g_Q[s];                       // xyz immutable this pass
        float  dd = ((const float*)&g_S[d])[3];   // dinv[d], never modified
        asm volatile("red.global.add.v4.f32 [%0], {%1,%2,%3,%4};"
                     :: "l"(&g_S[d]), "f"(q.x), "f"(q.y), "f"(q.z), "f"(0.0f)
                     : "memory");
        asm volatile("red.global.add.f32 [%0], %1;"
                     :: "l"(&((float*)&g_Q[s])[3]), "f"(dd)
                     : "memory");
    }
}

// layer-1 + layer-2 accumulation, grid-stride, weights in smem, partial stores:
//   a = dinv*(S + sx);  h1 = relu(a @ W1 + b1);  acc += (w*dinv)*h1
__global__ void __launch_bounds__(256) k_layer1(const float* __restrict__ W1,
                                                const float* __restrict__ b1) {
    __shared__ float w1s[48];
    __shared__ float b1s[16];
    if (threadIdx.x < 48) w1s[threadIdx.x] = W1[threadIdx.x];
    if (threadIdx.x < 16) b1s[threadIdx.x] = b1[threadIdx.x];
    __syncthreads();

    float acc[16];
    #pragma unroll
    for (int j = 0; j < 16; j++) acc[j] = 0.f;

    int stride = gridDim.x * blockDim.x;
    for (int v = blockIdx.x * blockDim.x + threadIdx.x; v < NN; v += stride) {
        float4 S = g_S[v];           // S.xyz, dinv
        float4 Q = g_Q[v];           // sx.xyz, w
        float  d = S.w;
        float  wv = Q.w * d;
        float a0 = d * (S.x + Q.x);
        float a1 = d * (S.y + Q.y);
        float a2 = d * (S.z + Q.z);
        #pragma unroll
        for (int j = 0; j < 16; j++) {
            float h = b1s[j] + a0 * w1s[j] + a1 * w1s[16 + j] + a2 * w1s[32 + j];
            acc[j] += wv * fmaxf(h, 0.f);
        }
    }

    // warp reduce 16 floats
    #pragma unroll
    for (int j = 0; j < 16; j++) {
        #pragma unroll
        for (int o = 16; o > 0; o >>= 1)
            acc[j] += __shfl_down_sync(0xffffffffu, acc[j], o);
    }
    __shared__ float sm[8][16];
    int lane = threadIdx.x & 31, w = threadIdx.x >> 5;
    if (lane == 0) {
        #pragma unroll
        for (int j = 0; j < 16; j++) sm[w][j] = acc[j];
    }
    __syncthreads();
    if (threadIdx.x < 16) {
        float s = 0.f;
        #pragma unroll
        for (int ww = 0; ww < 8; ww++) s += sm[ww][threadIdx.x];
        g_part[blockIdx.x][threadIdx.x] = s;     // plain store
    }
}

// reduce partials; out[j] = (sum16/N) @ W2 + b2
__global__ void k_final(const float* __restrict__ W2, const float* __restrict__ b2,
                        float* __restrict__ out) {
    __shared__ float red[16][16];
    __shared__ float sum16[16];
    int tid = threadIdx.x;          // 256 threads
    int j = tid & 15;
    int g = tid >> 4;
    float s = 0.f;
    for (int b = g; b < L1_BLOCKS; b += 16)
        s += g_part[b][j];
    red[g][j] = s;
    __syncthreads();
    if (tid < 16) {
        float t = 0.f;
        #pragma unroll
        for (int gg = 0; gg < 16; gg++) t += red[gg][tid];
        sum16[tid] = t * (1.0f / (float)NN);
    }
    __syncthreads();
    if (tid < 32) {
        float o = __ldg(&b2[tid]);
        #pragma unroll
        for (int k = 0; k < 16; k++)
            o += sum16[k] * __ldg(&W2[k * 32 + tid]);
        out[tid] = o;
    }
}

// ---------------------------------------------------------------------------
extern "C" void kernel_launch(void* const* d_in, const int* in_sizes, int n_in,
                              void* d_out, int out_size) {
    const float* x   = (const float*)d_in[0];
    const int*   ei  = (const int*)d_in[1];
    const float* W1  = (const float*)d_in[2];
    const float* b1  = (const float*)d_in[3];
    const float* W2  = (const float*)d_in[4];
    const float* b2  = (const float*)d_in[5];
    float*       out = (float*)d_out;

    int E = in_sizes[1] / 2;
    const int* src = ei;
    const int* dst = ei + E;

    int nb_edges = (E + 255) / 256;
    if (nb_edges > 9600) nb_edges = 9600;

    k_hist<<<nb_edges, 256>>>(dst, E);
    k_node_prep<<<(NN + 255) / 256, 256>>>(x);
    k_scatter<<<nb_edges, 256>>>(src, dst, E);
    k_layer1<<<L1_BLOCKS, 256>>>(W1, b1);
    k_final<<<1, 256>>>(W2, b2, out);
}

// round 8
// speedup vs baseline: 1.1342x; 1.1342x over previous
#include <cuda_runtime.h>

#define NN 100000
#define L1_BLOCKS 592   // layer1 grid; 8 warps/block, 2 nodes/warp/iter

// ---- scratch (static __device__ globals; no allocation) ----
__device__ int    g_deg[NN];             // zero at load; node_prep resets each run
__device__ float  g_dinv[NN];
__device__ float4 g_S[NN];               // layer-1 accumulator (w lane = junk)
__device__ float4 g_Q[NN];               // {sx.xyz, w-accum (init dinv)}
__device__ float  g_part[L1_BLOCKS][16]; // per-block layer-2 partials

// ---------------------------------------------------------------------------
// degree histogram over dst (self-loop added in node_prep)
__global__ void k_hist(const int* __restrict__ dst, int E) {
    int i      = blockIdx.x * blockDim.x + threadIdx.x;
    int stride = gridDim.x * blockDim.x;
    for (int e = i; e < E; e += stride) {
        atomicAdd(&g_deg[dst[e]], 1);
    }
}

// per-node: dinv = rsqrt(deg+1); Q = {dinv*x, dinv}; S = 0; reset deg
__global__ void k_node_prep(const float* __restrict__ x) {
    int v = blockIdx.x * blockDim.x + threadIdx.x;
    if (v >= NN) return;
    float d = rsqrtf((float)(g_deg[v] + 1));
    g_deg[v]  = 0;                       // deterministic across graph replays
    g_dinv[v] = d;
    g_S[v] = make_float4(0.f, 0.f, 0.f, 0.f);
    g_Q[v] = make_float4(d * x[3 * v + 0], d * x[3 * v + 1], d * x[3 * v + 2], d);
}

// fused edge pass, 4 divergent lanes per edge (proven 65us form):
//   gather Q[s] (16B), gather dinv[d] (4B, separate array),
//   red.v4 S[d] += Q[s]  (w lane junk), red Q[s].w += dinv[d]
__global__ void k_scatter(const int* __restrict__ src,
                          const int* __restrict__ dst, int E) {
    int i      = blockIdx.x * blockDim.x + threadIdx.x;
    int stride = gridDim.x * blockDim.x;
    for (int e = i; e < E; e += stride) {
        int s = src[e];
        int d = dst[e];
        float4 q  = g_Q[s];              // xyz immutable this pass
        float  dd = g_dinv[d];
        asm volatile("red.global.add.v4.f32 [%0], {%1,%2,%3,%4};"
                     :: "l"(&g_S[d]), "f"(q.x), "f"(q.y), "f"(q.z), "f"(q.w)
                     : "memory");
        asm volatile("red.global.add.f32 [%0], %1;"
                     :: "l"(&((float*)&g_Q[s])[3]), "f"(dd)
                     : "memory");
    }
}

// layer-1 + layer-2 accumulation, ONE FEATURE PER LANE (low reg pressure):
//   lanes 0-15 -> features of node v0, lanes 16-31 -> node v1 (per warp)
//   a = dinv*(S + sx);  h1[j] = relu(a.W1[:,j] + b1[j]);  acc_j += (w*dinv)*h1[j]
__global__ void __launch_bounds__(256) k_layer1(const float* __restrict__ W1,
                                                const float* __restrict__ b1) {
    __shared__ float w1s[48];
    __shared__ float b1s[16];
    if (threadIdx.x < 48) w1s[threadIdx.x] = W1[threadIdx.x];
    if (threadIdx.x < 16) b1s[threadIdx.x] = b1[threadIdx.x];
    __syncthreads();

    int w    = threadIdx.x >> 5;         // warp 0..7
    int lane = threadIdx.x & 31;
    int half = lane >> 4;                // 0 or 1
    int j    = lane & 15;                // feature

    float wj0 = w1s[j], wj1 = w1s[16 + j], wj2 = w1s[32 + j], bj = b1s[j];

    float acc = 0.f;
    int v      = (blockIdx.x * 8 + w) * 2 + half;
    int stride = gridDim.x * 8 * 2;
    for (; v < NN; v += stride) {
        float4 S = g_S[v];               // broadcast across 16 lanes
        float4 Q = g_Q[v];
        float  d = Q.w - (Q.w - g_dinv[v]);  // avoid: just load dinv
        d = g_dinv[v];
        float wv = Q.w * d;
        float a0 = d * (S.x + Q.x);
        float a1 = d * (S.y + Q.y);
        float a2 = d * (S.z + Q.z);
        float h = bj + a0 * wj0 + a1 * wj1 + a2 * wj2;
        acc += wv * fmaxf(h, 0.f);
    }

    // fold half 1 onto half 0
    acc += __shfl_down_sync(0xffffffffu, acc, 16);

    __shared__ float sm[8][16];
    if (half == 0) sm[w][j] = acc;
    __syncthreads();
    if (threadIdx.x < 16) {
        float s = 0.f;
        #pragma unroll
        for (int ww = 0; ww < 8; ww++) s += sm[ww][threadIdx.x];
        g_part[blockIdx.x][threadIdx.x] = s;   // plain store
    }
}

// reduce partials; out[j] = (sum16/N) @ W2 + b2
__global__ void k_final(const float* __restrict__ W2, const float* __restrict__ b2,
                        float* __restrict__ out) {
    __shared__ float red[16][16];
    __shared__ float sum16[16];
    int tid = threadIdx.x;          // 256 threads
    int j = tid & 15;
    int g = tid >> 4;
    float s = 0.f;
    for (int b = g; b < L1_BLOCKS; b += 16)
        s += g_part[b][j];
    red[g][j] = s;
    __syncthreads();
    if (tid < 16) {
        float t = 0.f;
        #pragma unroll
        for (int gg = 0; gg < 16; gg++) t += red[gg][tid];
        sum16[tid] = t * (1.0f / (float)NN);
    }
    __syncthreads();
    if (tid < 32) {
        float o = __ldg(&b2[tid]);
        #pragma unroll
        for (int k = 0; k < 16; k++)
            o += sum16[k] * __ldg(&W2[k * 32 + tid]);
        out[tid] = o;
    }
}

// ---------------------------------------------------------------------------
extern "C" void kernel_launch(void* const* d_in, const int* in_sizes, int n_in,
                              void* d_out, int out_size) {
    const float* x   = (const float*)d_in[0];
    const int*   ei  = (const int*)d_in[1];
    const float* W1  = (const float*)d_in[2];
    const float* b1  = (const float*)d_in[3];
    const float* W2  = (const float*)d_in[4];
    const float* b2  = (const float*)d_in[5];
    float*       out = (float*)d_out;

    int E = in_sizes[1] / 2;
    const int* src = ei;
    const int* dst = ei + E;

    int nb_edges = (E + 255) / 256;
    if (nb_edges > 9600) nb_edges = 9600;

    k_hist<<<nb_edges, 256>>>(dst, E);
    k_node_prep<<<(NN + 255) / 256, 256>>>(x);
    k_scatter<<<nb_edges, 256>>>(src, dst, E);
    k_layer1<<<L1_BLOCKS, 256>>>(W1, b1);
    k_final<<<1, 256>>>(W2, b2, out);
}